// round 4
// baseline (speedup 1.0000x reference)
#include <cuda_runtime.h>
#include <cuda_fp16.h>
#include <cstdint>

#define R_TOT   48
#define N_NODES 1000
#define RN      48000          // R_TOT * N_NODES
#define E_IN    12000
#define F_DIM   64
#define HC      256            // H * C
#define H_HEADS 4
#define E_MAX   (E_IN + N_NODES)

// ---------------- scratch (static device globals; no allocation) -------------
// h stored as fp16: [RN][32] uint4, each uint4 = 8 halves (16B), lane l owns uint4 #l
__device__ uint4 g_hv[(size_t)RN * 32];
__device__ float g_asrc[RN * H_HEADS];
__device__ float g_adst[RN * H_HEADS];
__device__ int   g_cnt[N_NODES];        // zero-init (BSS); re-zeroed by k_scatter
__device__ int   g_rowptr[N_NODES + 1];
__device__ int   g_cursor[N_NODES];
__device__ int   g_csrc[E_MAX];
__device__ int   g_is32;

// ---------------- packed fp32x2 FMA (sm_100+) --------------------------------
union F2U { unsigned long long u; float2 f; };
__device__ __forceinline__ unsigned long long fma2(unsigned long long a,
                                                   unsigned long long b,
                                                   unsigned long long c) {
    unsigned long long d;
    asm("fma.rn.f32x2 %0, %1, %2, %3;" : "=l"(d) : "l"(a), "l"(b), "l"(c));
    return d;
}

// ---------------- CSR build: 3 multi-SM micro-kernels -------------------------
// Original self-loops dropped (reference masks them to -inf => exp == 0 exactly);
// one added self-loop per node occupies the first CSR slot deterministically.

// Width detect by sampling: if edge_index is int64 (values < 1000), EVERY odd
// 32-bit word is zero. 32 sampled odd words all zero on int32 random data has
// probability ~1e-96. Sampled positions stay within the first 24000 words
// (valid for both widths).
__device__ __forceinline__ int detect_is32_warp(const int* e32, int lane) {
    int f = (e32[2 * (lane * 375) + 1] != 0);
    unsigned b = __ballot_sync(0xffffffffu, f);
    return b != 0;
}

__global__ __launch_bounds__(256) void k_count(const void* __restrict__ ei) {
    __shared__ int s_is32;
    const int* e32 = (const int*)ei;
    const long long* e64 = (const long long*)ei;
    int t = threadIdx.x;
    if (t < 32) {
        int is32 = detect_is32_warp(e32, t);
        if (t == 0) {
            s_is32 = is32;
            if (blockIdx.x == 0) g_is32 = is32;
        }
    }
    __syncthreads();
    int is32 = s_is32;
    int e = blockIdx.x * 256 + t;
    if (e < E_IN) {
        int s = is32 ? e32[e] : (int)e64[e];
        int d = is32 ? e32[E_IN + e] : (int)e64[E_IN + e];
        if (s != d) atomicAdd(&g_cnt[d], 1);   // spread over 1000 L2 addresses
    }
}

__global__ __launch_bounds__(1024) void k_scan() {   // one block
    __shared__ int s_wsum[32];
    int t = threadIdx.x, lane = t & 31, wid = t >> 5;
    int v = (t < N_NODES) ? (g_cnt[t] + 1) : 0;      // +1 = added self-loop
    int x = v;
#pragma unroll
    for (int o = 1; o < 32; o <<= 1) {
        int y = __shfl_up_sync(0xffffffffu, x, o);
        if (lane >= o) x += y;
    }
    if (lane == 31) s_wsum[wid] = x;
    __syncthreads();
    if (wid == 0) {
        int w = s_wsum[lane];
#pragma unroll
        for (int o = 1; o < 32; o <<= 1) {
            int y = __shfl_up_sync(0xffffffffu, w, o);
            if (lane >= o) w += y;
        }
        s_wsum[lane] = w;
    }
    __syncthreads();
    int incl = x + (wid ? s_wsum[wid - 1] : 0);
    int excl = incl - v;
    if (t < N_NODES) {
        g_rowptr[t] = excl;
        g_csrc[excl] = t;                // self-loop first, deterministic
        g_cursor[t] = excl + 1;
    }
    if (t == N_NODES - 1) g_rowptr[N_NODES] = incl;
}

__global__ __launch_bounds__(256) void k_scatter(const void* __restrict__ ei) {
    const int* e32 = (const int*)ei;
    const long long* e64 = (const long long*)ei;
    int t = threadIdx.x;
    int e = blockIdx.x * 256 + t;
    int is32 = g_is32;
    if (e < E_IN) {
        int s = is32 ? e32[e] : (int)e64[e];
        int d = is32 ? e32[E_IN + e] : (int)e64[E_IN + e];
        if (s != d) {
            int p = atomicAdd(&g_cursor[d], 1);
            g_csrc[p] = s;
        }
    }
    if (e < N_NODES) g_cnt[e] = 0;       // reset for next graph replay
}

// ---------------- projection GEMM + attention logits --------------------------
// Block: 256 threads = 8 warps; block tile = 64 rows x 256 cols, K = 64.
// Warp handles 8 rows; lane l owns output columns [8l, 8l+8) (one head per lane).
// h written as fp16 (16B per lane per row); logits stay fp32.
__global__ __launch_bounds__(256) void k_gemm(const float* __restrict__ x,
                                              const float* __restrict__ W,
                                              const float* __restrict__ attS,
                                              const float* __restrict__ attD) {
    __shared__ float sX[64][F_DIM + 4];
    __shared__ float sAS[HC], sAD[HC];

    int t = threadIdx.x, warp = t >> 5, lane = t & 31;
    int rowBase = blockIdx.x * 64;

    for (int i = t; i < 64 * 16; i += 256) {
        int rr = i >> 4, j = i & 15;
        float4 v = ((const float4*)(x + (size_t)(rowBase + rr) * F_DIM))[j];
        *(float4*)&sX[rr][j * 4] = v;
    }
    if (t < HC) { sAS[t] = attS[t]; sAD[t] = attD[t]; }
    __syncthreads();

    int c0 = lane * 8;
    unsigned long long acc[8][4];
#pragma unroll
    for (int rr = 0; rr < 8; rr++)
#pragma unroll
        for (int j = 0; j < 4; j++) acc[rr][j] = 0ULL;

#pragma unroll 8
    for (int f = 0; f < F_DIM; f++) {
        const float4* wp = (const float4*)(W + f * HC + c0);  // L1-resident (64 KB)
        float4 wa = wp[0], wb = wp[1];
        F2U b0, b1, b2, b3;
        b0.f = make_float2(wa.x, wa.y); b1.f = make_float2(wa.z, wa.w);
        b2.f = make_float2(wb.x, wb.y); b3.f = make_float2(wb.z, wb.w);
#pragma unroll
        for (int rr = 0; rr < 8; rr++) {
            F2U xb; float xv = sX[warp * 8 + rr][f];
            xb.f = make_float2(xv, xv);
            acc[rr][0] = fma2(xb.u, b0.u, acc[rr][0]);
            acc[rr][1] = fma2(xb.u, b1.u, acc[rr][1]);
            acc[rr][2] = fma2(xb.u, b2.u, acc[rr][2]);
            acc[rr][3] = fma2(xb.u, b3.u, acc[rr][3]);
        }
    }

    int head = c0 >> 6;
#pragma unroll
    for (int rr = 0; rr < 8; rr++) {
        int row = rowBase + warp * 8 + rr;
        float a[8];
#pragma unroll
        for (int j = 0; j < 4; j++) {
            F2U u; u.u = acc[rr][j];
            a[2 * j] = u.f.x; a[2 * j + 1] = u.f.y;
        }
        float as = 0.f, ad = 0.f;
#pragma unroll
        for (int k = 0; k < 8; k++) {
            as += a[k] * sAS[c0 + k];
            ad += a[k] * sAD[c0 + k];
        }
#pragma unroll
        for (int off = 1; off < 8; off <<= 1) {
            as += __shfl_xor_sync(0xffffffffu, as, off);
            ad += __shfl_xor_sync(0xffffffffu, ad, off);
        }
        if ((lane & 7) == 0) {
            g_asrc[row * 4 + head] = as;
            g_adst[row * 4 + head] = ad;
        }
        __half2 p0 = __floats2half2_rn(a[0], a[1]);
        __half2 p1 = __floats2half2_rn(a[2], a[3]);
        __half2 p2 = __floats2half2_rn(a[4], a[5]);
        __half2 p3 = __floats2half2_rn(a[6], a[7]);
        uint4 u;
        u.x = *reinterpret_cast<unsigned*>(&p0);
        u.y = *reinterpret_cast<unsigned*>(&p1);
        u.z = *reinterpret_cast<unsigned*>(&p2);
        u.w = *reinterpret_cast<unsigned*>(&p3);
        g_hv[(size_t)row * 32 + lane] = u;
    }
}

// ---------------- softmax aggregation (one warp per (r, dst)) -----------------
// Two-phase per 32-edge chunk:
//   A: lane l handles edge chunk+l — coalesced csrc load, one 16B logit gather,
//      4 exps, weights to smem, per-lane den partials.
//   B: per edge: 1 shfl (src) + 1 broadcast LDS (weight) + 1 LDG.128 (h) + FMAs.
// No max-shift: logits bounded far below 80 => exp(e) equals the reference's
// shifted softmax exactly in effect; den eps 1e-16 matches reference.
__global__ __launch_bounds__(256) void k_agg(const float* __restrict__ bias,
                                             float* __restrict__ out) {
    __shared__ float4 sw[8][32];
    int warp = threadIdx.x >> 5, lane = threadIdx.x & 31;
    int gw = blockIdx.x * 8 + warp;
    if (gw >= RN) return;
    int r = gw / N_NODES, i = gw - r * N_NODES;
    int head = lane >> 3;
    int start = g_rowptr[i], end = g_rowptr[i + 1];
    int rbase = r * N_NODES;

    float4 ad4 = *(const float4*)(g_adst + (size_t)(rbase + i) * 4);

    float d0 = 0.f, d1 = 0.f, d2 = 0.f, d3 = 0.f;
    float a0 = 0.f, a1 = 0.f, a2 = 0.f, a3 = 0.f;
    float a4 = 0.f, a5 = 0.f, a6 = 0.f, a7 = 0.f;

    for (int chunk = start; chunk < end; chunk += 32) {
        int cdeg = min(32, end - chunk);
        int kk = chunk + lane;
        int s_l = g_csrc[min(kk, end - 1)];
        float4 as4 = *(const float4*)(g_asrc + (size_t)(rbase + s_l) * 4);
        float e0 = as4.x + ad4.x, e1 = as4.y + ad4.y;
        float e2 = as4.z + ad4.z, e3 = as4.w + ad4.w;
        e0 = (e0 > 0.f) ? e0 : 0.2f * e0;
        e1 = (e1 > 0.f) ? e1 : 0.2f * e1;
        e2 = (e2 > 0.f) ? e2 : 0.2f * e2;
        e3 = (e3 > 0.f) ? e3 : 0.2f * e3;
        float w0 = __expf(fminf(e0, 80.f));
        float w1 = __expf(fminf(e1, 80.f));
        float w2 = __expf(fminf(e2, 80.f));
        float w3 = __expf(fminf(e3, 80.f));
        if (lane >= cdeg) { w0 = w1 = w2 = w3 = 0.f; }
        d0 += w0; d1 += w1; d2 += w2; d3 += w3;
        sw[warp][lane] = make_float4(w0, w1, w2, w3);
        __syncwarp();

#pragma unroll 4
        for (int k = 0; k < cdeg; k++) {
            int s = __shfl_sync(0xffffffffu, s_l, k);
            float w = ((const float*)&sw[warp][k])[head];   // 4-way broadcast
            uint4 u = g_hv[(size_t)(rbase + s) * 32 + lane];  // 16B/lane, 512B/warp
            float2 f0 = __half22float2(*reinterpret_cast<__half2*>(&u.x));
            float2 f1 = __half22float2(*reinterpret_cast<__half2*>(&u.y));
            float2 f2 = __half22float2(*reinterpret_cast<__half2*>(&u.z));
            float2 f3 = __half22float2(*reinterpret_cast<__half2*>(&u.w));
            a0 += w * f0.x; a1 += w * f0.y; a2 += w * f1.x; a3 += w * f1.y;
            a4 += w * f2.x; a5 += w * f2.y; a6 += w * f3.x; a7 += w * f3.y;
        }
        __syncwarp();
    }

    // reduce per-head denominators across lanes
#pragma unroll
    for (int off = 1; off < 32; off <<= 1) {
        d0 += __shfl_xor_sync(0xffffffffu, d0, off);
        d1 += __shfl_xor_sync(0xffffffffu, d1, off);
        d2 += __shfl_xor_sync(0xffffffffu, d2, off);
        d3 += __shfl_xor_sync(0xffffffffu, d3, off);
    }
    float dh = (head == 0) ? d0 : (head == 1) ? d1 : (head == 2) ? d2 : d3;
    float inv = 1.0f / (dh + 1e-16f);

    float a[8] = {a0 * inv, a1 * inv, a2 * inv, a3 * inv,
                  a4 * inv, a5 * inv, a6 * inv, a7 * inv};

    // head mean: lanes l, l^8, l^16, l^24 hold same channel, different heads
#pragma unroll
    for (int k = 0; k < 8; k++) {
        a[k] += __shfl_xor_sync(0xffffffffu, a[k], 8);
        a[k] += __shfl_xor_sync(0xffffffffu, a[k], 16);
    }

    if (lane < 8) {
        const float4* bp = (const float4*)bias;
        float4 b0 = bp[lane * 2], b1 = bp[lane * 2 + 1];
        float4 o0 = make_float4(0.25f * a[0] + b0.x, 0.25f * a[1] + b0.y,
                                0.25f * a[2] + b0.z, 0.25f * a[3] + b0.w);
        float4 o1 = make_float4(0.25f * a[4] + b1.x, 0.25f * a[5] + b1.y,
                                0.25f * a[6] + b1.z, 0.25f * a[7] + b1.w);
        float4* op = (float4*)(out + (size_t)(rbase + i) * 64 + lane * 8);
        op[0] = o0;
        op[1] = o1;
    }
}

// ---------------- launch ------------------------------------------------------
extern "C" void kernel_launch(void* const* d_in, const int* in_sizes, int n_in,
                              void* d_out, int out_size) {
    const float* x    = (const float*)d_in[0];
    const void*  ei   = d_in[1];
    const float* W    = (const float*)d_in[2];
    const float* attS = (const float*)d_in[3];
    const float* attD = (const float*)d_in[4];
    const float* bias = (const float*)d_in[5];
    float* out = (float*)d_out;

    k_count<<<(E_IN + 255) / 256, 256>>>(ei);
    k_scan<<<1, 1024>>>();
    k_scatter<<<(E_IN + 255) / 256, 256>>>(ei);
    k_gemm<<<RN / 64, 256>>>(x, W, attS, attD);
    k_agg<<<RN / 8, 256>>>(bias, out);
}

// round 5
// speedup vs baseline: 1.1198x; 1.1198x over previous
#include <cuda_runtime.h>
#include <cuda_fp16.h>
#include <cstdint>

#define R_TOT   48
#define N_NODES 1000
#define RN      48000          // R_TOT * N_NODES
#define E_IN    12000
#define F_DIM   64
#define HC      256            // H * C
#define H_HEADS 4
#define E_MAX   (E_IN + N_NODES)

// ---------------- scratch (static device globals; no allocation) -------------
// h stored as fp16: [RN][32] uint4, each uint4 = 8 halves (16B), lane l owns uint4 #l
__device__ uint4 g_hv[(size_t)RN * 32];
__device__ float g_asrc[RN * H_HEADS];
__device__ float g_adst[RN * H_HEADS];
__device__ int   g_cnt[N_NODES];        // zero-init (BSS); re-zeroed by k_scatter
__device__ int   g_rowptr[N_NODES + 1];
__device__ int   g_cursor[N_NODES];
__device__ int   g_csrc[E_MAX];
__device__ int   g_is32;

// ---------------- packed fp32x2 FMA (sm_100+) --------------------------------
union F2U { unsigned long long u; float2 f; };
__device__ __forceinline__ unsigned long long fma2(unsigned long long a,
                                                   unsigned long long b,
                                                   unsigned long long c) {
    unsigned long long d;
    asm("fma.rn.f32x2 %0, %1, %2, %3;" : "=l"(d) : "l"(a), "l"(b), "l"(c));
    return d;
}

// ---------------- CSR build: 3 multi-SM micro-kernels -------------------------
// Original self-loops dropped (reference masks them to -inf => exp == 0 exactly);
// one added self-loop per node occupies the first CSR slot deterministically.

// Width detect by sampling: if edge_index is int64 (values < 1000), EVERY odd
// 32-bit word is zero. 32 sampled odd words all zero on int32 random data has
// probability ~1e-96. Sampled positions stay within the first 24000 words.
__device__ __forceinline__ int detect_is32_warp(const int* e32, int lane) {
    int f = (e32[2 * (lane * 375) + 1] != 0);
    unsigned b = __ballot_sync(0xffffffffu, f);
    return b != 0;
}

__global__ __launch_bounds__(256) void k_count(const void* __restrict__ ei) {
    __shared__ int s_is32;
    const int* e32 = (const int*)ei;
    const long long* e64 = (const long long*)ei;
    int t = threadIdx.x;
    if (t < 32) {
        int is32 = detect_is32_warp(e32, t);
        if (t == 0) {
            s_is32 = is32;
            if (blockIdx.x == 0) g_is32 = is32;
        }
    }
    __syncthreads();
    int is32 = s_is32;
    int e = blockIdx.x * 256 + t;
    if (e < E_IN) {
        int s = is32 ? e32[e] : (int)e64[e];
        int d = is32 ? e32[E_IN + e] : (int)e64[E_IN + e];
        if (s != d) atomicAdd(&g_cnt[d], 1);   // spread over 1000 L2 addresses
    }
}

__global__ __launch_bounds__(1024) void k_scan() {   // one block
    __shared__ int s_wsum[32];
    int t = threadIdx.x, lane = t & 31, wid = t >> 5;
    int v = (t < N_NODES) ? (g_cnt[t] + 1) : 0;      // +1 = added self-loop
    int x = v;
#pragma unroll
    for (int o = 1; o < 32; o <<= 1) {
        int y = __shfl_up_sync(0xffffffffu, x, o);
        if (lane >= o) x += y;
    }
    if (lane == 31) s_wsum[wid] = x;
    __syncthreads();
    if (wid == 0) {
        int w = s_wsum[lane];
#pragma unroll
        for (int o = 1; o < 32; o <<= 1) {
            int y = __shfl_up_sync(0xffffffffu, w, o);
            if (lane >= o) w += y;
        }
        s_wsum[lane] = w;
    }
    __syncthreads();
    int incl = x + (wid ? s_wsum[wid - 1] : 0);
    int excl = incl - v;
    if (t < N_NODES) {
        g_rowptr[t] = excl;
        g_csrc[excl] = t;                // self-loop first, deterministic
        g_cursor[t] = excl + 1;
    }
    if (t == N_NODES - 1) g_rowptr[N_NODES] = incl;
}

__global__ __launch_bounds__(256) void k_scatter(const void* __restrict__ ei) {
    const int* e32 = (const int*)ei;
    const long long* e64 = (const long long*)ei;
    int t = threadIdx.x;
    int e = blockIdx.x * 256 + t;
    int is32 = g_is32;
    if (e < E_IN) {
        int s = is32 ? e32[e] : (int)e64[e];
        int d = is32 ? e32[E_IN + e] : (int)e64[E_IN + e];
        if (s != d) {
            int p = atomicAdd(&g_cursor[d], 1);
            g_csrc[p] = s;
        }
    }
    if (e < N_NODES) g_cnt[e] = 0;       // reset for next graph replay
}

// ---------------- projection GEMM + attention logits --------------------------
// Block: 256 threads = 8 warps; tile 64 rows x 256 cols, K=64.
// Warp: 8 rows; lane l: cols [8l,8l+8) (one head per lane).
// K chunked by 4: stage 4 W rows in regs (8 LDG.128), read x via one LDS.128
// broadcast per row per chunk. __launch_bounds__(256,2) -> 2 blocks/SM.
__global__ __launch_bounds__(256, 2) void k_gemm(const float* __restrict__ x,
                                                 const float* __restrict__ W,
                                                 const float* __restrict__ attS,
                                                 const float* __restrict__ attD) {
    __shared__ float sX[64][72];          // 72 floats/row: float4-aligned chunks
    __shared__ float sAS[HC], sAD[HC];

    int t = threadIdx.x, warp = t >> 5, lane = t & 31;
    int rowBase = blockIdx.x * 64;

    for (int i = t; i < 64 * 16; i += 256) {
        int rr = i >> 4, j = i & 15;
        float4 v = ((const float4*)(x + (size_t)(rowBase + rr) * F_DIM))[j];
        *(float4*)&sX[rr][j * 4] = v;
    }
    if (t < HC) { sAS[t] = attS[t]; sAD[t] = attD[t]; }
    __syncthreads();

    int c0 = lane * 8;
    unsigned long long acc[8][4];
#pragma unroll
    for (int rr = 0; rr < 8; rr++)
#pragma unroll
        for (int j = 0; j < 4; j++) acc[rr][j] = 0ULL;

    const float4* wbase = (const float4*)(W + c0);   // row stride 64 float4

#pragma unroll 4
    for (int f4 = 0; f4 < F_DIM; f4 += 4) {
        // stage W rows f4..f4+3 (8 x LDG.128, L1-resident)
        F2U wb[4][4];
#pragma unroll
        for (int j = 0; j < 4; j++) {
            float4 wa = wbase[(f4 + j) * 64];
            float4 wc = wbase[(f4 + j) * 64 + 1];
            wb[j][0].f = make_float2(wa.x, wa.y);
            wb[j][1].f = make_float2(wa.z, wa.w);
            wb[j][2].f = make_float2(wc.x, wc.y);
            wb[j][3].f = make_float2(wc.z, wc.w);
        }
#pragma unroll
        for (int rr = 0; rr < 8; rr++) {
            float4 xv = *(const float4*)&sX[warp * 8 + rr][f4];  // broadcast LDS.128
            float xs[4] = {xv.x, xv.y, xv.z, xv.w};
#pragma unroll
            for (int j = 0; j < 4; j++) {
                F2U xb; xb.f = make_float2(xs[j], xs[j]);
                acc[rr][0] = fma2(xb.u, wb[j][0].u, acc[rr][0]);
                acc[rr][1] = fma2(xb.u, wb[j][1].u, acc[rr][1]);
                acc[rr][2] = fma2(xb.u, wb[j][2].u, acc[rr][2]);
                acc[rr][3] = fma2(xb.u, wb[j][3].u, acc[rr][3]);
            }
        }
    }

    int head = c0 >> 6;
#pragma unroll
    for (int rr = 0; rr < 8; rr++) {
        int row = rowBase + warp * 8 + rr;
        float a[8];
#pragma unroll
        for (int j = 0; j < 4; j++) {
            F2U u; u.u = acc[rr][j];
            a[2 * j] = u.f.x; a[2 * j + 1] = u.f.y;
        }
        float as = 0.f, ad = 0.f;
#pragma unroll
        for (int k = 0; k < 8; k++) {
            as += a[k] * sAS[c0 + k];
            ad += a[k] * sAD[c0 + k];
        }
#pragma unroll
        for (int off = 1; off < 8; off <<= 1) {
            as += __shfl_xor_sync(0xffffffffu, as, off);
            ad += __shfl_xor_sync(0xffffffffu, ad, off);
        }
        if ((lane & 7) == 0) {
            g_asrc[row * 4 + head] = as;
            g_adst[row * 4 + head] = ad;
        }
        __half2 p0 = __floats2half2_rn(a[0], a[1]);
        __half2 p1 = __floats2half2_rn(a[2], a[3]);
        __half2 p2 = __floats2half2_rn(a[4], a[5]);
        __half2 p3 = __floats2half2_rn(a[6], a[7]);
        uint4 u;
        u.x = *reinterpret_cast<unsigned*>(&p0);
        u.y = *reinterpret_cast<unsigned*>(&p1);
        u.z = *reinterpret_cast<unsigned*>(&p2);
        u.w = *reinterpret_cast<unsigned*>(&p3);
        g_hv[(size_t)row * 32 + lane] = u;
    }
}

// ---------------- softmax aggregation (single pass, one warp per (r, dst)) ----
// R3 form (fastest measured). No max-shift: logits bounded far below 80, so
// exp(e) equals the reference's shifted softmax; den eps 1e-16 matches ref.
__global__ __launch_bounds__(256) void k_agg(const float* __restrict__ bias,
                                             float* __restrict__ out) {
    int gw = (blockIdx.x * blockDim.x + threadIdx.x) >> 5;
    int lane = threadIdx.x & 31;
    if (gw >= RN) return;
    int r = gw / N_NODES, i = gw - r * N_NODES;
    int head = lane >> 3;
    int start = g_rowptr[i], end = g_rowptr[i + 1];
    int rbase = r * N_NODES;

    float adsth = g_adst[(rbase + i) * 4 + head];

    float den = 1e-16f;
    float a0 = 0.f, a1 = 0.f, a2 = 0.f, a3 = 0.f;
    float a4 = 0.f, a5 = 0.f, a6 = 0.f, a7 = 0.f;

#pragma unroll 2
    for (int k = start; k < end; k++) {
        int s = g_csrc[k];
        float e = g_asrc[(rbase + s) * 4 + head] + adsth;
        e = (e > 0.f) ? e : 0.2f * e;
        float w = __expf(fminf(e, 80.f));
        den += w;
        uint4 u = g_hv[(size_t)(rbase + s) * 32 + lane];   // 16B/lane, 512B/warp
        float2 f0 = __half22float2(*reinterpret_cast<__half2*>(&u.x));
        float2 f1 = __half22float2(*reinterpret_cast<__half2*>(&u.y));
        float2 f2 = __half22float2(*reinterpret_cast<__half2*>(&u.z));
        float2 f3 = __half22float2(*reinterpret_cast<__half2*>(&u.w));
        a0 += w * f0.x; a1 += w * f0.y; a2 += w * f1.x; a3 += w * f1.y;
        a4 += w * f2.x; a5 += w * f2.y; a6 += w * f3.x; a7 += w * f3.y;
    }

    float inv = 1.0f / den;
    float a[8] = {a0 * inv, a1 * inv, a2 * inv, a3 * inv,
                  a4 * inv, a5 * inv, a6 * inv, a7 * inv};

    // head mean: lanes l, l^8, l^16, l^24 hold same channel, different heads
#pragma unroll
    for (int k = 0; k < 8; k++) {
        a[k] += __shfl_xor_sync(0xffffffffu, a[k], 8);
        a[k] += __shfl_xor_sync(0xffffffffu, a[k], 16);
    }

    if (lane < 8) {
        const float4* bp = (const float4*)bias;
        float4 b0 = bp[lane * 2], b1 = bp[lane * 2 + 1];
        float4 o0 = make_float4(0.25f * a[0] + b0.x, 0.25f * a[1] + b0.y,
                                0.25f * a[2] + b0.z, 0.25f * a[3] + b0.w);
        float4 o1 = make_float4(0.25f * a[4] + b1.x, 0.25f * a[5] + b1.y,
                                0.25f * a[6] + b1.z, 0.25f * a[7] + b1.w);
        float4* op = (float4*)(out + (size_t)(rbase + i) * 64 + lane * 8);
        op[0] = o0;
        op[1] = o1;
    }
}

// ---------------- launch ------------------------------------------------------
extern "C" void kernel_launch(void* const* d_in, const int* in_sizes, int n_in,
                              void* d_out, int out_size) {
    const float* x    = (const float*)d_in[0];
    const void*  ei   = d_in[1];
    const float* W    = (const float*)d_in[2];
    const float* attS = (const float*)d_in[3];
    const float* attD = (const float*)d_in[4];
    const float* bias = (const float*)d_in[5];
    float* out = (float*)d_out;

    k_count<<<(E_IN + 255) / 256, 256>>>(ei);
    k_scan<<<1, 1024>>>();
    k_scatter<<<(E_IN + 255) / 256, 256>>>(ei);
    k_gemm<<<RN / 64, 256>>>(x, W, attS, attD);
    k_agg<<<RN / 8, 256>>>(bias, out);
}